// round 1
// baseline (speedup 1.0000x reference)
#include <cuda_runtime.h>
#include <math.h>

// Problem constants (fixed by reference setup_inputs)
#define BB 64
#define AA 5
#define CC 20
#define HH 64
#define WW 64
#define HWSZ 4096           // H*W
#define NT 50               // targets per batch
#define CH 26               // 6 + C channels per anchor

#define COORD_SCALE 5.0f
#define OBJ_SCALE   5.0f
#define THETA_SCALE 5.0f

// Scratch (allocation-free rule: __device__ globals)
__device__ double g_acc[4];              // 0:coord 1:conf 2:ce 3:theta
__device__ int    g_nobj;
__device__ int    g_ent_flat[BB * NT];   // best_n*HW + cell (within batch)
__device__ float  g_ent_vals[BB * NT][6];// tc0..tc3, tconf, ttheta
__device__ int    g_ent_cls[BB * NT];
__device__ unsigned char g_ent_valid[BB * NT];

__device__ __forceinline__ float sl1(float x) {
    float ax = fabsf(x);
    return ax < 1.0f ? 0.5f * x * x : ax - 0.5f;
}
__device__ __forceinline__ float sigmoidf(float x) {
    return 1.0f / (1.0f + expf(-x));
}

// ---------------------------------------------------------------------------
// Kernel 1: build sparse targets. One thread per batch, serial over n so that
// last-write-wins ordering matches JAX scatter semantics (no collisions exist
// in practice since cells are a permutation slice, but keep the check cheap).
// ---------------------------------------------------------------------------
__global__ void k_build(const float* __restrict__ target,
                        const float* __restrict__ anchors) {
    int b = threadIdx.x;
    if (b == 0) {
        g_acc[0] = 0.0; g_acc[1] = 0.0; g_acc[2] = 0.0; g_acc[3] = 0.0;
        g_nobj = 0;
    }
    if (b >= BB) return;

    for (int n = 0; n < NT; ++n) {
        const float* t = target + (size_t)(b * NT + n) * 6;
        float gx = t[0] * WW;
        float gy = t[1] * HH;
        float gw = t[2] * WW;
        float gh = t[3] * HH;
        float gtheta = t[4] * (float)(M_PI / 8.0);

        // argmax over anchors (first max wins -> strict >)
        int   bn = 0;
        float bi = -2.0f;
        #pragma unroll
        for (int a = 0; a < AA; ++a) {
            float iou = cosf(0.25f * (gtheta - anchors[a * 3 + 2]));
            if (iou > bi) { bi = iou; bn = a; }
        }

        int gi = (int)gx; gi = gi < 0 ? 0 : (gi > WW - 1 ? WW - 1 : gi);
        int gj = (int)gy; gj = gj < 0 ? 0 : (gj > HH - 1 ? HH - 1 : gj);
        int cell = gj * WW + gi;

        int e = b * NT + n;
        g_ent_flat[e]    = bn * HWSZ + cell;
        g_ent_vals[e][0] = gx - (float)gi;
        g_ent_vals[e][1] = gy - (float)gj;
        g_ent_vals[e][2] = logf(fmaxf(gw, 1.0f) / anchors[bn * 3 + 0]);
        g_ent_vals[e][3] = logf(fmaxf(gh, 1.0f) / anchors[bn * 3 + 1]);
        g_ent_vals[e][4] = bi;                          // tconf = best_iou
        g_ent_vals[e][5] = gtheta - anchors[bn * 3 + 2];// ttheta
        g_ent_cls[e]     = (int)t[5];
    }
    // last-wins validity (duplicates impossible by construction, but exact)
    for (int n = 0; n < NT; ++n) {
        int f = g_ent_flat[b * NT + n];
        unsigned char v = 1;
        for (int m = n + 1; m < NT; ++m)
            if (g_ent_flat[b * NT + m] == f) { v = 0; break; }
        g_ent_valid[b * NT + n] = v;
    }
}

// ---------------------------------------------------------------------------
// Kernel 2a: no-object conf loss over ALL B*A*HW cells (channel 4 planes only).
// Obj cells are corrected in k_obj. This is the only HBM-significant kernel:
// 5.24 MB of reads.
// ---------------------------------------------------------------------------
__global__ void k_conf(const float* __restrict__ out) {
    int i = blockIdx.x * blockDim.x + threadIdx.x;   // 0 .. B*A*HW-1
    int ba = i >> 12;                                 // (b*A + a)
    int hw = i & (HWSZ - 1);
    float x = out[((size_t)ba * CH + 4) * HWSZ + hw];
    float s = sigmoidf(x);
    float v = sl1(s);                                 // conf_mask=1, tconf=0

    // warp + block reduce, one double atomic per block
    #pragma unroll
    for (int off = 16; off > 0; off >>= 1)
        v += __shfl_down_sync(0xFFFFFFFFu, v, off);
    __shared__ float sh[8];
    int lane = threadIdx.x & 31, warp = threadIdx.x >> 5;
    if (lane == 0) sh[warp] = v;
    __syncthreads();
    if (warp == 0) {
        float w = (lane < (blockDim.x >> 5)) ? sh[lane] : 0.0f;
        #pragma unroll
        for (int off = 4; off > 0; off >>= 1)
            w += __shfl_down_sync(0xFFFFFFFFu, w, off);
        if (lane == 0) atomicAdd(&g_acc[1], (double)w);
    }
}

// ---------------------------------------------------------------------------
// Kernel 2b: per object entry (<=3200): coord, conf correction, CE, theta.
// ---------------------------------------------------------------------------
__global__ void k_obj(const float* __restrict__ out) {
    int e = blockIdx.x * blockDim.x + threadIdx.x;
    if (e >= BB * NT) return;
    if (!g_ent_valid[e]) return;

    int b    = e / NT;
    int fl   = g_ent_flat[e];
    int a    = fl >> 12;
    int cell = fl & (HWSZ - 1);
    const float* base = out + ((size_t)(b * AA + a) * CH) * HWSZ + cell;

    float o0 = base[0 * HWSZ];
    float o1 = base[1 * HWSZ];
    float o2 = base[2 * HWSZ];
    float o3 = base[3 * HWSZ];
    float o4 = base[4 * HWSZ];
    float o5 = base[5 * HWSZ];

    float sx = sigmoidf(o0);
    float sy = sigmoidf(o1);
    float coord = sl1(sx - g_ent_vals[e][0]) + sl1(sy - g_ent_vals[e][1]) +
                  sl1(o2 - g_ent_vals[e][2]) + sl1(o3 - g_ent_vals[e][3]);

    float sc = sigmoidf(o4);
    // replace the non-obj term counted in k_conf with the obj term
    float confc = sl1(OBJ_SCALE * (sc - g_ent_vals[e][4])) - sl1(sc);

    float th = sl1(o5 - g_ent_vals[e][5]);

    // log-softmax CE over 20 classes
    float lg[CC];
    float mx = -1e30f;
    #pragma unroll
    for (int k = 0; k < CC; ++k) {
        lg[k] = base[(size_t)(6 + k) * HWSZ];
        mx = fmaxf(mx, lg[k]);
    }
    float se = 0.0f;
    #pragma unroll
    for (int k = 0; k < CC; ++k) se += expf(lg[k] - mx);
    float lse = mx + logf(se);
    float ce = lse - lg[g_ent_cls[e]];

    atomicAdd(&g_acc[0], (double)coord);
    atomicAdd(&g_acc[1], (double)confc);
    atomicAdd(&g_acc[2], (double)ce);
    atomicAdd(&g_acc[3], (double)th);
    atomicAdd(&g_nobj, 1);
}

// ---------------------------------------------------------------------------
// Kernel 3: finalize the 5 scalars.
// ---------------------------------------------------------------------------
__global__ void k_final(float* __restrict__ outv) {
    double n_coord = (double)BB * AA * 4 * HWSZ;   // 5,242,880
    double n_conf  = (double)BB * AA * HWSZ;       // 1,310,720
    double n_obj   = (double)(g_nobj > 0 ? g_nobj : 1);

    float loss_coord = (float)(COORD_SCALE * g_acc[0] / n_coord);
    float loss_conf  = (float)(g_acc[1] / n_conf);
    float loss_cls   = (float)(2.0 * g_acc[2] / n_obj);
    float loss_theta = (float)(THETA_SCALE * g_acc[3] / n_obj);
    float loss_tot   = loss_coord + loss_conf + loss_cls + loss_theta;

    outv[0] = loss_tot;
    outv[1] = loss_coord;
    outv[2] = loss_conf;
    outv[3] = loss_cls;
    outv[4] = loss_theta;
}

extern "C" void kernel_launch(void* const* d_in, const int* in_sizes, int n_in,
                              void* d_out, int out_size) {
    const float* output  = (const float*)d_in[0];
    const float* target  = (const float*)d_in[1];
    const float* anchors = (const float*)d_in[2];
    float* outv = (float*)d_out;

    k_build<<<1, 64>>>(target, anchors);
    k_conf<<<(BB * AA * HWSZ) / 256, 256>>>(output);
    k_obj<<<(BB * NT + 255) / 256, 256>>>(output);
    k_final<<<1, 1>>>(outv);
}

// round 2
// speedup vs baseline: 2.6602x; 2.6602x over previous
#include <cuda_runtime.h>
#include <math.h>

// Problem constants (fixed by reference setup_inputs)
#define BB 64
#define AA 5
#define CC 20
#define HH 64
#define WW 64
#define HWSZ 4096           // H*W
#define NT 50               // targets per batch
#define CH 26               // 6 + C channels per anchor
#define NOBJ_ENT (BB * NT)  // 3200

#define COORD_SCALE 5.0f
#define OBJ_SCALE   5.0f
#define THETA_SCALE 5.0f

#define NB_CONF 320                   // one block per (b,a) conf plane
#define NB_OBJ  13                    // ceil(3200/256)
#define NBLK    (NB_CONF + NB_OBJ)    // 333

// Persistent device state. Zero-initialized at load; the finalizer resets it
// to zero at the end of EVERY call, so each graph replay sees zeros.
__device__ double       g_acc[4];     // 0:coord 1:conf 2:ce 3:theta
__device__ int          g_nobj;
__device__ unsigned int g_done;

__device__ __forceinline__ float sl1(float x) {
    float ax = fabsf(x);
    return ax < 1.0f ? 0.5f * x * x : ax - 0.5f;
}
__device__ __forceinline__ float sigmoidf(float x) {
    return 1.0f / (1.0f + expf(-x));
}

// Block-reduce a float, result valid in thread 0.
__device__ __forceinline__ float block_sum(float v, float* sh) {
    #pragma unroll
    for (int off = 16; off > 0; off >>= 1)
        v += __shfl_down_sync(0xFFFFFFFFu, v, off);
    int lane = threadIdx.x & 31, warp = threadIdx.x >> 5;
    if (lane == 0) sh[warp] = v;
    __syncthreads();
    if (warp == 0) {
        float w = (lane < 8) ? sh[lane] : 0.0f;
        #pragma unroll
        for (int off = 4; off > 0; off >>= 1)
            w += __shfl_down_sync(0xFFFFFFFFu, w, off);
        v = w;
    }
    __syncthreads();   // sh reused by caller
    return v;
}

__global__ void __launch_bounds__(256)
k_fused(const float* __restrict__ out,
        const float* __restrict__ target,
        const float* __restrict__ anchors,
        float* __restrict__ outv) {
    __shared__ float sh[8];

    if (blockIdx.x < NB_CONF) {
        // ---------------- conf planes: blocks 0..319, one (b,a) plane each ---
        const float4* p = (const float4*)(out + ((size_t)blockIdx.x * CH + 4) * HWSZ);
        float s = 0.0f;
        #pragma unroll
        for (int j = 0; j < 4; ++j) {
            float4 v = p[threadIdx.x + j * 256];
            s += sl1(sigmoidf(v.x)) + sl1(sigmoidf(v.y)) +
                 sl1(sigmoidf(v.z)) + sl1(sigmoidf(v.w));
        }
        float tot = block_sum(s, sh);
        if (threadIdx.x == 0) atomicAdd(&g_acc[1], (double)tot);
    } else {
        // ---------------- object entries: blocks 320..332 --------------------
        int e = (blockIdx.x - NB_CONF) * 256 + threadIdx.x;
        float coord = 0.0f, confc = 0.0f, ce = 0.0f, th = 0.0f;
        int cnt = 0;

        if (e < NOBJ_ENT) {
            int b = e / NT, n = e - b * NT;
            const float* t = target + (size_t)e * 6;
            float gx = t[0] * WW;
            float gy = t[1] * HH;
            float gw = t[2] * WW;
            float gh = t[3] * HH;
            float gtheta = t[4] * (float)(M_PI / 8.0);

            // argmax over anchors (first max wins -> strict >)
            int bn = 0; float bi = -2.0f;
            #pragma unroll
            for (int a = 0; a < AA; ++a) {
                float iou = cosf(0.25f * (gtheta - anchors[a * 3 + 2]));
                if (iou > bi) { bi = iou; bn = a; }
            }

            int gi = (int)gx; gi = gi < 0 ? 0 : (gi > WW - 1 ? WW - 1 : gi);
            int gj = (int)gy; gj = gj < 0 ? 0 : (gj > HH - 1 ? HH - 1 : gj);
            int cell = gj * WW + gi;

            // last-write-wins validity: a LATER entry m with the same flat
            // index (same cell AND same best anchor) shadows this one.
            // Cell equality is the necessary condition and is cheap to test;
            // the anchor recompute happens only on a cell match (never in
            // practice: cells are a permutation slice).
            bool valid = true;
            const float* tb = target + (size_t)(b * NT) * 6;
            for (int m = n + 1; m < NT; ++m) {
                float mx = tb[m * 6 + 0] * WW;
                float my = tb[m * 6 + 1] * HH;
                int mi = (int)mx; mi = mi < 0 ? 0 : (mi > WW - 1 ? WW - 1 : mi);
                int mj = (int)my; mj = mj < 0 ? 0 : (mj > HH - 1 ? HH - 1 : mj);
                if (mj * WW + mi == cell) {
                    float mt = tb[m * 6 + 4] * (float)(M_PI / 8.0);
                    int mbn = 0; float mbi = -2.0f;
                    #pragma unroll
                    for (int a = 0; a < AA; ++a) {
                        float iou = cosf(0.25f * (mt - anchors[a * 3 + 2]));
                        if (iou > mbi) { mbi = iou; mbn = a; }
                    }
                    if (mbn == bn) { valid = false; break; }
                }
            }

            if (valid) {
                cnt = 1;
                float tc0 = gx - (float)gi;
                float tc1 = gy - (float)gj;
                float tc2 = logf(fmaxf(gw, 1.0f) / anchors[bn * 3 + 0]);
                float tc3 = logf(fmaxf(gh, 1.0f) / anchors[bn * 3 + 1]);
                float tth = gtheta - anchors[bn * 3 + 2];

                const float* base = out + ((size_t)(b * AA + bn) * CH) * HWSZ + cell;
                float o0 = base[0 * HWSZ];
                float o1 = base[1 * HWSZ];
                float o2 = base[2 * HWSZ];
                float o3 = base[3 * HWSZ];
                float o4 = base[4 * HWSZ];
                float o5 = base[5 * HWSZ];

                coord = sl1(sigmoidf(o0) - tc0) + sl1(sigmoidf(o1) - tc1) +
                        sl1(o2 - tc2) + sl1(o3 - tc3);

                float sc = sigmoidf(o4);
                confc = sl1(OBJ_SCALE * (sc - bi)) - sl1(sc);

                th = sl1(o5 - tth);

                // log-softmax CE over 20 classes
                float lg[CC];
                float mxv = -1e30f;
                #pragma unroll
                for (int k = 0; k < CC; ++k) {
                    lg[k] = base[(size_t)(6 + k) * HWSZ];
                    mxv = fmaxf(mxv, lg[k]);
                }
                float se = 0.0f;
                #pragma unroll
                for (int k = 0; k < CC; ++k) se += expf(lg[k] - mxv);
                int cls = (int)t[5];
                ce = (mxv + logf(se)) - lg[cls];
            }
        }

        float rc = block_sum(coord, sh);
        float rf = block_sum(confc, sh);
        float re = block_sum(ce, sh);
        float rt = block_sum(th, sh);
        float rn = block_sum((float)cnt, sh);
        if (threadIdx.x == 0) {
            atomicAdd(&g_acc[0], (double)rc);
            atomicAdd(&g_acc[1], (double)rf);
            atomicAdd(&g_acc[2], (double)re);
            atomicAdd(&g_acc[3], (double)rt);
            atomicAdd(&g_nobj, (int)(rn + 0.5f));
        }
    }

    // ---------------- last-block finalizer -----------------------------------
    __threadfence();
    __syncthreads();
    if (threadIdx.x == 0) {
        unsigned int ticket = atomicAdd(&g_done, 1u);
        if (ticket == NBLK - 1) {
            // atomic fetches force coherent L2 reads of the accumulators
            double a0 = atomicAdd(&g_acc[0], 0.0);
            double a1 = atomicAdd(&g_acc[1], 0.0);
            double a2 = atomicAdd(&g_acc[2], 0.0);
            double a3 = atomicAdd(&g_acc[3], 0.0);
            int    no = atomicAdd(&g_nobj, 0);

            double n_coord = (double)BB * AA * 4 * HWSZ;   // 5,242,880
            double n_conf  = (double)BB * AA * HWSZ;       // 1,310,720
            double n_obj   = (double)(no > 0 ? no : 1);

            float loss_coord = (float)(COORD_SCALE * a0 / n_coord);
            float loss_conf  = (float)(a1 / n_conf);
            float loss_cls   = (float)(2.0 * a2 / n_obj);
            float loss_theta = (float)(THETA_SCALE * a3 / n_obj);

            outv[0] = loss_coord + loss_conf + loss_cls + loss_theta;
            outv[1] = loss_coord;
            outv[2] = loss_conf;
            outv[3] = loss_cls;
            outv[4] = loss_theta;

            // reset state for the next (graph-replayed) call
            g_acc[0] = 0.0; g_acc[1] = 0.0; g_acc[2] = 0.0; g_acc[3] = 0.0;
            g_nobj = 0;
            __threadfence();
            g_done = 0u;
        }
    }
}

extern "C" void kernel_launch(void* const* d_in, const int* in_sizes, int n_in,
                              void* d_out, int out_size) {
    const float* output  = (const float*)d_in[0];
    const float* target  = (const float*)d_in[1];
    const float* anchors = (const float*)d_in[2];
    float* outv = (float*)d_out;

    k_fused<<<NBLK, 256>>>(output, target, anchors, outv);
}

// round 5
// speedup vs baseline: 10.5899x; 3.9808x over previous
#include <cuda_runtime.h>
#include <math.h>

// Problem constants (fixed by reference setup_inputs)
#define BB 64
#define AA 5
#define CC 20
#define HH 64
#define WW 64
#define HWSZ 4096           // H*W
#define NT 50               // targets per batch
#define CH 26               // 6 + C channels per anchor
#define NOBJ_ENT (BB * NT)  // 3200

#define COORD_SCALE 5.0f
#define OBJ_SCALE   5.0f
#define THETA_SCALE 5.0f

// Grid layout: obj blocks first (long-latency scatter starts early),
// then conf blocks.
#define NB_OBJ   400                  // 8 warps/block, 1 warp per entry
#define NB_CONF  640                  // 2 blocks per (b,a) conf plane
#define NBLK     (NB_OBJ + NB_CONF)   // 1040

// Persistent device state; finalizer resets to zero every call (graph-safe).
__device__ double       g_acc[4][8];  // 0:coord 1:conf 2:ce 3:theta, 8 slots
__device__ int          g_nobj;
__device__ unsigned int g_done;

__device__ __forceinline__ float sl1(float x) {
    float ax = fabsf(x);
    return ax < 1.0f ? 0.5f * x * x : ax - 0.5f;
}
__device__ __forceinline__ float sigmoid_precise(float x) {
    return 1.0f / (1.0f + expf(-x));
}
__device__ __forceinline__ float rcp_approx(float x) {
    float r;
    asm("rcp.approx.f32 %0, %1;" : "=f"(r) : "f"(x));
    return r;
}

// sum over 4 elements of sl1(sigmoid(x)) = 0.5*sigmoid(x)^2, with ONE rcp
// for the whole group (batched reciprocal). 1.25 MUFU / element.
// sigmoid(x) in (0,1) so sl1 is always the quadratic branch (0.5 s^2).
// Clamp x >= -20 so the group product of (1+e^{-x}) cannot overflow;
// for x <= -20 sigmoid^2 ~ 1e-18, contribution is below fp32 noise anyway.
__device__ __forceinline__ float conf_group4(float4 v) {
    float x0 = fmaxf(v.x, -20.0f);
    float x1 = fmaxf(v.y, -20.0f);
    float x2 = fmaxf(v.z, -20.0f);
    float x3 = fmaxf(v.w, -20.0f);
    float t0 = 1.0f + __expf(-x0);
    float t1 = 1.0f + __expf(-x1);
    float t2 = 1.0f + __expf(-x2);
    float t3 = 1.0f + __expf(-x3);
    float t01 = t0 * t1, t23 = t2 * t3;
    float r   = rcp_approx(t01 * t23);
    float r01 = r * t23, r23 = r * t01;   // 1/(t0*t1), 1/(t2*t3)
    float i0 = r01 * t1, i1 = r01 * t0;   // 1/t0, 1/t1
    float i2 = r23 * t3, i3 = r23 * t2;   // 1/t2, 1/t3
    return 0.5f * (i0 * i0 + i1 * i1 + i2 * i2 + i3 * i3);
}

// Block-reduce a float, result valid in thread 0.
__device__ __forceinline__ float block_sum(float v, float* sh) {
    #pragma unroll
    for (int off = 16; off > 0; off >>= 1)
        v += __shfl_down_sync(0xFFFFFFFFu, v, off);
    int lane = threadIdx.x & 31, warp = threadIdx.x >> 5;
    if (lane == 0) sh[warp] = v;
    __syncthreads();
    if (warp == 0) {
        float w = (lane < 8) ? sh[lane] : 0.0f;
        #pragma unroll
        for (int off = 4; off > 0; off >>= 1)
            w += __shfl_down_sync(0xFFFFFFFFu, w, off);
        v = w;
    }
    __syncthreads();
    return v;
}

__device__ __forceinline__ float warp_bfly_sum(float v) {
    #pragma unroll
    for (int off = 16; off > 0; off >>= 1)
        v += __shfl_xor_sync(0xFFFFFFFFu, v, off);
    return v;
}
__device__ __forceinline__ float warp_bfly_max(float v) {
    #pragma unroll
    for (int off = 16; off > 0; off >>= 1)
        v = fmaxf(v, __shfl_xor_sync(0xFFFFFFFFu, v, off));
    return v;
}

__global__ void __launch_bounds__(256)
k_fused(const float* __restrict__ out,
        const float* __restrict__ target,
        const float* __restrict__ anchors,
        float* __restrict__ outv) {
    __shared__ float sh[8];
    int slot = blockIdx.x & 7;

    if (blockIdx.x < NB_OBJ) {
        // ================= object entries: 1 warp per entry ==================
        int lane = threadIdx.x & 31;
        int e = blockIdx.x * 8 + (threadIdx.x >> 5);   // entry id, < 3200
        int b = e / NT, n = e - b * NT;

        // anchor table (15 floats) loaded once per thread, kept in registers
        float aw0 = anchors[0],  ah0 = anchors[1],  at0 = anchors[2];
        float aw1 = anchors[3],  ah1 = anchors[4],  at1 = anchors[5];
        float aw2 = anchors[6],  ah2 = anchors[7],  at2 = anchors[8];
        float aw3 = anchors[9],  ah3 = anchors[10], at3 = anchors[11];
        float aw4 = anchors[12], ah4 = anchors[13], at4 = anchors[14];
        float atb[AA] = {at0, at1, at2, at3, at4};
        float awb[AA] = {aw0, aw1, aw2, aw3, aw4};
        float ahb[AA] = {ah0, ah1, ah2, ah3, ah4};

        // every lane computes per-entry params (broadcast loads, L1-cheap)
        const float* t = target + (size_t)e * 6;
        float gx = t[0] * WW;
        float gy = t[1] * HH;
        float gw = t[2] * WW;
        float gh = t[3] * HH;
        float gtheta = t[4] * (float)(M_PI / 8.0);
        int   cls = (int)t[5];

        int bn = 0; float bi = -2.0f;
        #pragma unroll
        for (int a = 0; a < AA; ++a) {
            float iou = cosf(0.25f * (gtheta - atb[a]));
            if (iou > bi) { bi = iou; bn = a; }
        }

        int gi = (int)gx; gi = gi < 0 ? 0 : (gi > WW - 1 ? WW - 1 : gi);
        int gj = (int)gy; gj = gj < 0 ? 0 : (gj > HH - 1 ? HH - 1 : gj);
        int cell = gj * WW + gi;

        // last-write-wins shadow check, lane-parallel over later entries m.
        // cell equality is the cheap necessary condition; anchor argmax only
        // recomputed on a cell match (never happens: cells are a permutation).
        bool shadowed = false;
        const float* tb = target + (size_t)(b * NT) * 6;
        for (int m = n + 1 + lane; m < NT; m += 32) {
            float mx = tb[m * 6 + 0] * WW;
            float my = tb[m * 6 + 1] * HH;
            int mi = (int)mx; mi = mi < 0 ? 0 : (mi > WW - 1 ? WW - 1 : mi);
            int mj = (int)my; mj = mj < 0 ? 0 : (mj > HH - 1 ? HH - 1 : mj);
            if (mj * WW + mi == cell) {
                float mt = tb[m * 6 + 4] * (float)(M_PI / 8.0);
                int mbn = 0; float mbi = -2.0f;
                #pragma unroll
                for (int a = 0; a < AA; ++a) {
                    float iou = cosf(0.25f * (mt - atb[a]));
                    if (iou > mbi) { mbi = iou; mbn = a; }
                }
                if (mbn == bn) shadowed = true;
            }
        }
        bool valid = (__ballot_sync(0xFFFFFFFFu, shadowed) == 0u);

        // lane-parallel channel gather: lane k reads channel k of this cell
        const float* base = out + ((size_t)(b * AA + bn) * CH) * HWSZ + cell;
        float v = (lane < CH) ? base[(size_t)lane * HWSZ] : 0.0f;

        float c_coord = 0.0f, c_conf = 0.0f, c_ce = 0.0f, c_th = 0.0f;
        if (valid) {
            // CE over logits (lanes 6..25)
            bool is_logit = (lane >= 6 && lane < CH);
            float mxv = warp_bfly_max(is_logit ? v : -1e30f);
            float ex  = is_logit ? expf(v - mxv) : 0.0f;
            float se  = warp_bfly_sum(ex);
            float lgc = __shfl_sync(0xFFFFFFFFu, v, 6 + cls);
            float ce  = (mxv + logf(se)) - lgc;

            if (lane == 0) {
                c_coord = sl1(sigmoid_precise(v) - (gx - (float)gi));
            } else if (lane == 1) {
                c_coord = sl1(sigmoid_precise(v) - (gy - (float)gj));
            } else if (lane == 2) {
                c_coord = sl1(v - logf(fmaxf(gw, 1.0f) / awb[bn]));
            } else if (lane == 3) {
                c_coord = sl1(v - logf(fmaxf(gh, 1.0f) / ahb[bn]));
            } else if (lane == 4) {
                float sc = sigmoid_precise(v);
                c_conf = sl1(OBJ_SCALE * (sc - bi)) - sl1(sc);
            } else if (lane == 5) {
                c_th = sl1(v - (gtheta - atb[bn]));
            } else if (lane == 6) {
                c_ce = ce;
            }
        }

        float rc = block_sum(c_coord, sh);
        float rf = block_sum(c_conf, sh);
        float re = block_sum(c_ce, sh);
        float rt = block_sum(c_th, sh);
        float rn = block_sum((lane == 0 && valid) ? 1.0f : 0.0f, sh);
        if (threadIdx.x == 0) {
            atomicAdd(&g_acc[0][slot], (double)rc);
            atomicAdd(&g_acc[1][slot], (double)rf);
            atomicAdd(&g_acc[2][slot], (double)re);
            atomicAdd(&g_acc[3][slot], (double)rt);
            atomicAdd(&g_nobj, (int)(rn + 0.5f));
        }
    } else {
        // ================= conf planes: 2 blocks per (b,a) plane =============
        int cb = blockIdx.x - NB_OBJ;          // 0..639
        int plane = cb >> 1;                   // (b*A + a)
        int half  = cb & 1;
        const float4* p = (const float4*)(out + ((size_t)plane * CH + 4) * HWSZ)
                          + half * 512;
        float4 v0 = p[threadIdx.x];
        float4 v1 = p[threadIdx.x + 256];
        float s = conf_group4(v0) + conf_group4(v1);

        float tot = block_sum(s, sh);
        if (threadIdx.x == 0) atomicAdd(&g_acc[1][slot], (double)tot);
    }

    // ================= last-block finalizer ==================================
    __threadfence();
    __syncthreads();
    if (threadIdx.x == 0) {
        unsigned int ticket = atomicAdd(&g_done, 1u);
        if (ticket == NBLK - 1) {
            // atomic fetches force coherent reads of the accumulators
            double a[4];
            #pragma unroll
            for (int i = 0; i < 4; ++i) {
                double s = 0.0;
                #pragma unroll
                for (int j = 0; j < 8; ++j)
                    s += atomicAdd(&g_acc[i][j], 0.0);
                a[i] = s;
            }
            int no = atomicAdd(&g_nobj, 0);

            double n_coord = (double)BB * AA * 4 * HWSZ;   // 5,242,880
            double n_conf  = (double)BB * AA * HWSZ;       // 1,310,720
            double n_obj   = (double)(no > 0 ? no : 1);

            float loss_coord = (float)(COORD_SCALE * a[0] / n_coord);
            float loss_conf  = (float)(a[1] / n_conf);
            float loss_cls   = (float)(2.0 * a[2] / n_obj);
            float loss_theta = (float)(THETA_SCALE * a[3] / n_obj);

            outv[0] = loss_coord + loss_conf + loss_cls + loss_theta;
            outv[1] = loss_coord;
            outv[2] = loss_conf;
            outv[3] = loss_cls;
            outv[4] = loss_theta;

            // reset state for next graph replay
            #pragma unroll
            for (int i = 0; i < 4; ++i)
                #pragma unroll
                for (int j = 0; j < 8; ++j)
                    g_acc[i][j] = 0.0;
            g_nobj = 0;
            __threadfence();
            g_done = 0u;
        }
    }
}

extern "C" void kernel_launch(void* const* d_in, const int* in_sizes, int n_in,
                              void* d_out, int out_size) {
    const float* output  = (const float*)d_in[0];
    const float* target  = (const float*)d_in[1];
    const float* anchors = (const float*)d_in[2];
    float* outv = (float*)d_out;

    k_fused<<<NBLK, 256>>>(output, target, anchors, outv);
}